// round 14
// baseline (speedup 1.0000x reference)
#include <cuda_runtime.h>
#include <cuda_fp16.h>
#include <math.h>
#include <stdint.h>

// Problem constants
#define B_  4
#define T_  2048
#define C_  1024
#define H_  16
#define D_  64
#define M_  (B_*T_)     // 8192
#define N3  (3*C_)      // 3072

// fp16 copies of inputs (filled by convert pre-pass)
__device__ __half g_Xh[(size_t)M_*C_];
__device__ __half g_Wqh[(size_t)C_*N3];
__device__ __half g_Wph[(size_t)C_*C_];
// Scratch: Q pre-scaled 1/8 fp16 [B,H,T,D]; K fp16 [B,H,T,D];
// Vt fp16 transposed [B,H,D,T]; attention out fp16 [B,T,C].
__device__ __half g_Q[(size_t)M_*C_];
__device__ __half g_K[(size_t)M_*C_];
__device__ __half g_Vt[(size_t)M_*C_];
__device__ __half g_Oh[(size_t)M_*C_];

// ---------------------------------------------------------------------------
// Helpers
// ---------------------------------------------------------------------------
__device__ __forceinline__ void mma_f16(float c[4], const uint32_t a[4], const uint32_t b[2]) {
    asm volatile("mma.sync.aligned.m16n8k16.row.col.f32.f16.f16.f32 "
        "{%0,%1,%2,%3}, {%4,%5,%6,%7}, {%8,%9}, {%0,%1,%2,%3};"
        : "+f"(c[0]), "+f"(c[1]), "+f"(c[2]), "+f"(c[3])
        : "r"(a[0]), "r"(a[1]), "r"(a[2]), "r"(a[3]), "r"(b[0]), "r"(b[1]));
}
__device__ __forceinline__ void ldsm_x4(uint32_t r[4], uint32_t addr) {
    asm volatile("ldmatrix.sync.aligned.m8n8.x4.shared.b16 {%0,%1,%2,%3}, [%4];"
        : "=r"(r[0]), "=r"(r[1]), "=r"(r[2]), "=r"(r[3]) : "r"(addr));
}
__device__ __forceinline__ void ldsm_x4_t(uint32_t r[4], uint32_t addr) {
    asm volatile("ldmatrix.sync.aligned.m8n8.x4.trans.shared.b16 {%0,%1,%2,%3}, [%4];"
        : "=r"(r[0]), "=r"(r[1]), "=r"(r[2]), "=r"(r[3]) : "r"(addr));
}
__device__ __forceinline__ uint32_t pack_h2(float lo, float hi) {
    __half2 h = __floats2half2_rn(lo, hi);     // .x = lo (low 16b)
    return *(uint32_t*)&h;
}
__device__ __forceinline__ void cp16(uint32_t dst, const void* src) {
    asm volatile("cp.async.cg.shared.global [%0], [%1], 16;" :: "r"(dst), "l"(src));
}
#define CP_COMMIT() asm volatile("cp.async.commit_group;")
#define CP_WAIT0()  asm volatile("cp.async.wait_group 0;")
#define CP_WAIT1()  asm volatile("cp.async.wait_group 1;")

__device__ __forceinline__ uint32_t smem_u32(const void* p) {
    uint32_t a;
    asm("{ .reg .u64 t; cvta.to.shared.u64 t, %1; cvt.u32.u64 %0, t; }" : "=r"(a) : "l"(p));
    return a;
}

// ---------------------------------------------------------------------------
// Kernel 0: fp32 -> fp16 convert (grid-stride over float4)
// ---------------------------------------------------------------------------
__global__ void cvt_kernel(const float* __restrict__ s, __half* __restrict__ d, int n)
{
    const int stride = gridDim.x * blockDim.x;
    for (int i = blockIdx.x * blockDim.x + threadIdx.x; i * 4 < n; i += stride) {
        const float4 v = *(const float4*)(s + (size_t)i * 4);
        __half2 a = __floats2half2_rn(v.x, v.y);
        __half2 b = __floats2half2_rn(v.z, v.w);
        *(__half2*)(d + (size_t)i * 4)     = a;
        *(__half2*)(d + (size_t)i * 4 + 2) = b;
    }
}

// ---------------------------------------------------------------------------
// fp16 GEMM core: C[128x128] = A[M,K]h @ B[K,N]h. 256 thr / 8 warps,
// warp tile 64x32 (4 m-atoms x 4 n-atoms, m16n8k16) -> 16 warps/SM at occ 2.
// A frags: ldsm.x4; B frags: ldsm.x4.trans. 3-stage cp.async, 1 sync/chunk.
// ---------------------------------------------------------------------------
#define NSTG 3
#define ASTRIDE 40                         // fp16 elems (32 + 8 pad)
#define BSTRIDE 136                        // fp16 elems (128 + 8 pad)
#define AT_B (128*ASTRIDE*2)               // 10240 B
#define BT_B (32*BSTRIDE*2)                // 8704 B
#define STG_B (AT_B + BT_B)                // 18944 B
#define GEMM_SMEM (NSTG*STG_B)             // 56832 B

__device__ __forceinline__ void gemm_prefetch(
    uint32_t smb, const __half* __restrict__ A, int lda,
    const __half* __restrict__ B, int ldb, int m0, int n0,
    int ck, int stage, int tid)
{
    const uint32_t base = smb + (uint32_t)(stage*STG_B);
#pragma unroll
    for (int j = 0; j < 2; j++) {          // A: 128 rows x 32 h = 512 x 16B
        const int f = tid + j*256;
        const int ar = f >> 2, as8 = (f & 3) * 8;
        cp16(base + (uint32_t)(ar*ASTRIDE + as8)*2u,
             A + (size_t)(m0 + ar) * lda + ck*32 + as8);
    }
#pragma unroll
    for (int j = 0; j < 2; j++) {          // B: 32 rows x 128 h = 512 x 16B
        const int f = tid + j*256;
        const int br = f >> 4, bs8 = (f & 15) * 8;
        cp16(base + (uint32_t)AT_B + (uint32_t)(br*BSTRIDE + bs8)*2u,
             B + (size_t)(ck*32 + br) * ldb + n0 + bs8);
    }
    CP_COMMIT();
}

__device__ __forceinline__ void gemm_core(
    const __half* __restrict__ A, int lda,
    const __half* __restrict__ B, int ldb,
    int K, int m0, int n0, uint32_t smb, float acc[4][4][4])
{
    const int tid  = threadIdx.x;
    const int lane = tid & 31;
    const int warp = tid >> 5;             // 0..7
    const int wm = (warp >> 2) * 64;       // 2 m-groups
    const int wn = (warp & 3) * 32;        // 4 n-groups

    // A frag lanes: 0-15 rows 0-15 col k0; 16-31 rows 0-15 col k0+8
    const uint32_t a_lane = (uint32_t)((lane & 15)*ASTRIDE + ((lane >> 4) & 1)*8) * 2u;
    // B frag (trans) lanes: k-row (lane&7) + 8*((lane>>3)&1), n-col 8*((lane>>4)&1)
    const uint32_t b_lane = (uint32_t)(((lane & 7) + ((lane >> 3) & 1)*8)*BSTRIDE
                                       + ((lane >> 4) & 1)*8) * 2u;

    gemm_prefetch(smb, A, lda, B, ldb, m0, n0, 0, 0, tid);
    gemm_prefetch(smb, A, lda, B, ldb, m0, n0, 1, 1, tid);

    const int NCK = K / 32;
    for (int ck = 0; ck < NCK; ck++) {
        if (ck + 2 < NCK) { CP_WAIT1(); } else { CP_WAIT0(); }
        __syncthreads();
        if (ck + 2 < NCK)
            gemm_prefetch(smb, A, lda, B, ldb, m0, n0, ck + 2, (ck + 2) % NSTG, tid);

        const int stg = ck % NSTG;
        const uint32_t aBase = smb + (uint32_t)(stg*STG_B) + a_lane;
        const uint32_t bBase = smb + (uint32_t)(stg*STG_B + AT_B) + b_lane;
#pragma unroll
        for (int ks = 0; ks < 2; ks++) {
            const int k0 = ks*16;
            uint32_t af[4][4];
#pragma unroll
            for (int ma = 0; ma < 4; ma++)
                ldsm_x4(af[ma], aBase + (uint32_t)((wm + ma*16)*ASTRIDE + k0)*2u);
            uint32_t bf[2][4];
#pragma unroll
            for (int j = 0; j < 2; j++)    // 2 x ldsm_t covers 32 n-cols
                ldsm_x4_t(bf[j], bBase + (uint32_t)(k0*BSTRIDE + wn + j*16)*2u);
#pragma unroll
            for (int j = 0; j < 2; j++) {
                uint32_t b0[2] = { bf[j][0], bf[j][1] };
                uint32_t b1[2] = { bf[j][2], bf[j][3] };
#pragma unroll
                for (int ma = 0; ma < 4; ma++) {
                    mma_f16(acc[ma][2*j  ], af[ma], b0);
                    mma_f16(acc[ma][2*j+1], af[ma], b1);
                }
            }
        }
    }
}

// ---------------------------------------------------------------------------
// Kernel 1: QKV GEMM (fp16). Epilogue (fp32 + bias):
//   Q -> fp16((acc+b)/8); K -> fp16(acc+b); V -> fp16 transposed [b,h,d,t]
// ---------------------------------------------------------------------------
__global__ void __launch_bounds__(256, 2) qkv_kernel(const float* __restrict__ bias)
{
    extern __shared__ char smc[];
    const uint32_t smb = smem_u32(smc);
    float acc[4][4][4];
#pragma unroll
    for (int a = 0; a < 4; a++)
#pragma unroll
        for (int b = 0; b < 4; b++)
#pragma unroll
            for (int c = 0; c < 4; c++) acc[a][b][c] = 0.f;

    const int m0 = blockIdx.y * 128;
    const int n0 = blockIdx.x * 128;
    gemm_core(g_Xh, C_, g_Wqh, N3, C_, m0, n0, smb, acc);

    const int lane = threadIdx.x & 31;
    const int warp = threadIdx.x >> 5;
    const int g = lane >> 2, t = lane & 3;
    const int wm = (warp >> 2) * 64;
    const int wn = (warp & 3) * 32;

#pragma unroll
    for (int ma = 0; ma < 4; ma++) {
#pragma unroll
        for (int nb = 0; nb < 4; nb++) {
            const int col = n0 + wn + nb*8 + 2*t;
            const int part = col >> 10;
            const int cc = col & 1023;
            const int h = cc >> 6, d = cc & 63;
            const float b0 = bias[col], b1 = bias[col + 1];
#pragma unroll
            for (int half = 0; half < 2; half++) {
                const int row = m0 + wm + ma*16 + g + half*8;
                const int bb = row >> 11, tt = row & 2047;
                const float x0 = acc[ma][nb][half*2 + 0] + b0;
                const float x1 = acc[ma][nb][half*2 + 1] + b1;
                if (part == 2) {
                    const size_t vb = (size_t)(bb*H_ + h) * D_;
                    g_Vt[(vb + d    ) * T_ + tt] = __float2half_rn(x0);
                    g_Vt[(vb + d + 1) * T_ + tt] = __float2half_rn(x1);
                } else {
                    __half* dst = (part == 0) ? g_Q : g_K;
                    const float scl = (part == 0) ? 0.125f : 1.0f;
                    const size_t idx = ((((size_t)bb*H_ + h)*T_) + tt)*D_ + d;
                    *(__half2*)&dst[idx] = __floats2half2_rn(x0 * scl, x1 * scl);
                }
            }
        }
    }
}

// ---------------------------------------------------------------------------
// Kernel 3: proj GEMM (fp16 in, fp32 out)
// ---------------------------------------------------------------------------
__global__ void __launch_bounds__(256, 2) proj_kernel(
    const float* __restrict__ bias, float* __restrict__ out)
{
    extern __shared__ char smc[];
    const uint32_t smb = smem_u32(smc);
    float acc[4][4][4];
#pragma unroll
    for (int a = 0; a < 4; a++)
#pragma unroll
        for (int b = 0; b < 4; b++)
#pragma unroll
            for (int c = 0; c < 4; c++) acc[a][b][c] = 0.f;

    const int m0 = blockIdx.y * 128;
    const int n0 = blockIdx.x * 128;
    gemm_core(g_Oh, C_, g_Wph, C_, C_, m0, n0, smb, acc);

    const int lane = threadIdx.x & 31;
    const int warp = threadIdx.x >> 5;
    const int g = lane >> 2, t = lane & 3;
    const int wm = (warp >> 2) * 64;
    const int wn = (warp & 3) * 32;

#pragma unroll
    for (int ma = 0; ma < 4; ma++) {
#pragma unroll
        for (int nb = 0; nb < 4; nb++) {
            const int col = n0 + wn + nb*8 + 2*t;
            const float b0 = bias[col], b1 = bias[col + 1];
#pragma unroll
            for (int half = 0; half < 2; half++) {
                const int row = m0 + wm + ma*16 + g + half*8;
                float2 v;
                v.x = acc[ma][nb][half*2 + 0] + b0;
                v.y = acc[ma][nb][half*2 + 1] + b1;
                *(float2*)&out[(size_t)row*C_ + col] = v;
            }
        }
    }
}

// ---------------------------------------------------------------------------
// Kernel 2: flash attention (unchanged from R13 -- control).
// ---------------------------------------------------------------------------
#define QSTRIDE 72                         // fp16 elems (64 + 8 pad)
#define QS_B  0
#define Q_B_SZ (128*QSTRIDE*2)             // 18432
#define KS_B  Q_B_SZ                       // 18432
#define K_STG_B (64*QSTRIDE*2)             // 9216
#define VT_B  (KS_B + 2*K_STG_B)           // 36864
#define VT_STG_B (64*QSTRIDE*2)            // 9216
#define ATTN_SMEM (VT_B + 2*VT_STG_B)      // 55296

__global__ void __launch_bounds__(128, 2) attn_kernel()
{
    extern __shared__ char smc[];

    const int tid  = threadIdx.x;
    const int lane = tid & 31;
    const int warp = tid >> 5;                 // 0..3
    const int g = lane >> 2, t = lane & 3;
    const int q0 = blockIdx.x * 128;
    const int bh = blockIdx.y;
    const int qr = warp * 32;
    const uint32_t smb = smem_u32(smc);

    const __half* Qg = g_Q + ((size_t)bh*T_ + q0)*D_;
    const __half* Kg = g_K + (size_t)bh*T_*D_;
    const __half* Vtg = g_Vt + (size_t)bh*D_*T_;

    const uint32_t q_lane = (uint32_t)((lane & 15)*QSTRIDE + ((lane >> 4) & 1)*8) * 2u;
    const uint32_t k_lane = (uint32_t)(((lane & 7) + ((lane >> 4) & 1)*8)*QSTRIDE
                                       + ((lane >> 3) & 1)*8) * 2u;
    const uint32_t v_lane = k_lane;

    // Prefetch Q + K/Vt tile 0
#pragma unroll
    for (int it = 0; it < 8; it++) {
        const int f = tid + it*128;
        const int row = f >> 3, c8 = (f & 7) * 8;
        cp16(smb + (uint32_t)(QS_B + (row*QSTRIDE + c8)*2), Qg + (size_t)row*D_ + c8);
    }
#pragma unroll
    for (int it = 0; it < 4; it++) {
        const int f = tid + it*128;
        const int row = f >> 3, c8 = (f & 7) * 8;
        cp16(smb + (uint32_t)(KS_B + (row*QSTRIDE + c8)*2), Kg + (size_t)row*D_ + c8);
        cp16(smb + (uint32_t)(VT_B + (row*QSTRIDE + c8)*2), Vtg + (size_t)row*T_ + c8);
    }
    CP_COMMIT();

    float accO[2][8][4];
#pragma unroll
    for (int ma = 0; ma < 2; ma++)
#pragma unroll
        for (int nb = 0; nb < 8; nb++)
#pragma unroll
            for (int c = 0; c < 4; c++) accO[ma][nb][c] = 0.f;
    float lp[2][2] = {{0.f, 0.f}, {0.f, 0.f}};

    const int NT = T_/64;
    for (int kt = 0; kt < NT; kt++) {
        const int st = kt & 1;
        if (kt + 1 < NT) {
            __syncthreads();
            const int s2 = st ^ 1;
#pragma unroll
            for (int it = 0; it < 4; it++) {
                const int f = tid + it*128;
                const int row = f >> 3, c8 = (f & 7) * 8;
                cp16(smb + (uint32_t)(KS_B + s2*K_STG_B + (row*QSTRIDE + c8)*2),
                     Kg + (size_t)((kt+1)*64 + row)*D_ + c8);
                cp16(smb + (uint32_t)(VT_B + s2*VT_STG_B + (row*QSTRIDE + c8)*2),
                     Vtg + (size_t)row*T_ + (kt+1)*64 + c8);
            }
            CP_COMMIT();
            CP_WAIT1();
        } else {
            CP_WAIT0();
        }
        __syncthreads();

        const uint32_t qBase = smb + q_lane;
        const uint32_t kBase = smb + (uint32_t)(KS_B + st*K_STG_B) + k_lane;
        const uint32_t vBase = smb + (uint32_t)(VT_B + st*VT_STG_B) + v_lane;

        float sacc[2][8][4];
#pragma unroll
        for (int ma = 0; ma < 2; ma++)
#pragma unroll
            for (int nb = 0; nb < 8; nb++)
#pragma unroll
                for (int c = 0; c < 4; c++) sacc[ma][nb][c] = 0.f;

#pragma unroll
        for (int ks = 0; ks < 4; ks++) {
            const int k0 = ks*16;
            uint32_t af[2][4];
#pragma unroll
            for (int ma = 0; ma < 2; ma++)
                ldsm_x4(af[ma], qBase + (uint32_t)((qr + ma*16)*QSTRIDE + k0)*2u);
            uint32_t kf[4][4];
#pragma unroll
            for (int j = 0; j < 4; j++)
                ldsm_x4(kf[j], kBase + (uint32_t)(j*16*QSTRIDE + k0)*2u);
#pragma unroll
            for (int j = 0; j < 4; j++) {
                uint32_t b0[2] = { kf[j][0], kf[j][1] };
                uint32_t b1[2] = { kf[j][2], kf[j][3] };
                mma_f16(sacc[0][2*j  ], af[0], b0);
                mma_f16(sacc[1][2*j  ], af[1], b0);
                mma_f16(sacc[0][2*j+1], af[0], b1);
                mma_f16(sacc[1][2*j+1], af[1], b1);
            }
        }

        uint32_t pf[2][4][4];
#pragma unroll
        for (int ma = 0; ma < 2; ma++) {
#pragma unroll
            for (int nb = 0; nb < 8; nb++) {
                float p0 = __expf(sacc[ma][nb][0]);
                float p1 = __expf(sacc[ma][nb][1]);
                float p2 = __expf(sacc[ma][nb][2]);
                float p3 = __expf(sacc[ma][nb][3]);
                lp[ma][0] += p0 + p1;
                lp[ma][1] += p2 + p3;
                const int ks = nb >> 1, hi = nb & 1;
                pf[ma][ks][hi*2 + 0] = pack_h2(p0, p1);
                pf[ma][ks][hi*2 + 1] = pack_h2(p2, p3);
            }
        }

#pragma unroll
        for (int ks = 0; ks < 4; ks++) {
            const uint32_t kOff = (uint32_t)(ks*16) * 2u;
            uint32_t vf[4][4];
#pragma unroll
            for (int j = 0; j < 4; j++)
                ldsm_x4(vf[j], vBase + (uint32_t)(j*16*QSTRIDE)*2u + kOff);
#pragma unroll
            for (int j = 0; j < 4; j++) {
                uint32_t b0[2] = { vf[j][0], vf[j][1] };
                uint32_t b1[2] = { vf[j][2], vf[j][3] };
                mma_f16(accO[0][2*j  ], pf[0][ks], b0);
                mma_f16(accO[1][2*j  ], pf[1][ks], b0);
                mma_f16(accO[0][2*j+1], pf[0][ks], b1);
                mma_f16(accO[1][2*j+1], pf[1][ks], b1);
            }
        }
    }

    const int b = bh >> 4, h = bh & 15;
#pragma unroll
    for (int ma = 0; ma < 2; ma++) {
        float l0 = lp[ma][0], l1 = lp[ma][1];
        l0 += __shfl_xor_sync(0xffffffffu, l0, 1);
        l0 += __shfl_xor_sync(0xffffffffu, l0, 2);
        l1 += __shfl_xor_sync(0xffffffffu, l1, 1);
        l1 += __shfl_xor_sync(0xffffffffu, l1, 2);
        const float inv0 = 1.f / l0;
        const float inv1 = 1.f / l1;
        const int r0 = q0 + qr + ma*16 + g;
#pragma unroll
        for (int nb = 0; nb < 8; nb++) {
            const int col = h*D_ + nb*8 + 2*t;
            *(__half2*)&g_Oh[((size_t)b*T_ + r0    )*C_ + col] =
                __floats2half2_rn(accO[ma][nb][0]*inv0, accO[ma][nb][1]*inv0);
            *(__half2*)&g_Oh[((size_t)b*T_ + r0 + 8)*C_ + col] =
                __floats2half2_rn(accO[ma][nb][2]*inv1, accO[ma][nb][3]*inv1);
        }
    }
}

// ---------------------------------------------------------------------------
// Launch
// ---------------------------------------------------------------------------
extern "C" void kernel_launch(void* const* d_in, const int* in_sizes, int n_in,
                              void* d_out, int out_size)
{
    (void)in_sizes; (void)n_in; (void)out_size;
    const float* X      = (const float*)d_in[0];
    const float* W_qkv  = (const float*)d_in[1];
    const float* b_qkv  = (const float*)d_in[2];
    const float* W_proj = (const float*)d_in[3];
    const float* b_proj = (const float*)d_in[4];
    float* out = (float*)d_out;

    __half *xh, *wqh, *wph;
    cudaGetSymbolAddress((void**)&xh,  g_Xh);
    cudaGetSymbolAddress((void**)&wqh, g_Wqh);
    cudaGetSymbolAddress((void**)&wph, g_Wph);

    cudaFuncSetAttribute(qkv_kernel,  cudaFuncAttributeMaxDynamicSharedMemorySize, GEMM_SMEM);
    cudaFuncSetAttribute(proj_kernel, cudaFuncAttributeMaxDynamicSharedMemorySize, GEMM_SMEM);
    cudaFuncSetAttribute(attn_kernel, cudaFuncAttributeMaxDynamicSharedMemorySize, ATTN_SMEM);

    cvt_kernel<<<2048, 256>>>(X,      xh,  M_*C_);
    cvt_kernel<<<1024, 256>>>(W_qkv,  wqh, C_*N3);
    cvt_kernel<<<512,  256>>>(W_proj, wph, C_*C_);

    dim3 g1(N3/128, M_/128);            // (24, 64)
    qkv_kernel<<<g1, 256, GEMM_SMEM>>>(b_qkv);

    dim3 g2(T_/128, B_*H_);             // (16, 64)
    attn_kernel<<<g2, 128, ATTN_SMEM>>>();

    dim3 g3(C_/128, M_/128);            // (8, 64)
    proj_kernel<<<g3, 256, GEMM_SMEM>>>(b_proj, out);
}

// round 17
// speedup vs baseline: 1.0677x; 1.0677x over previous
#include <cuda_runtime.h>
#include <cuda_fp16.h>
#include <math.h>
#include <stdint.h>

// Problem constants
#define B_  4
#define T_  2048
#define C_  1024
#define H_  16
#define D_  64
#define M_  (B_*T_)     // 8192
#define N3  (3*C_)      // 3072

// fp16 copies of inputs (filled by convert pre-pass)
__device__ __half g_Xh[(size_t)M_*C_];
__device__ __half g_Wqh[(size_t)C_*N3];
__device__ __half g_Wph[(size_t)C_*C_];
// Scratch: Q pre-scaled 1/8 fp16 [B,H,T,D]; K fp16 [B,H,T,D];
// Vt fp16 transposed [B,H,D,T]; attention out fp16 [B,T,C].
__device__ __half g_Q[(size_t)M_*C_];
__device__ __half g_K[(size_t)M_*C_];
__device__ __half g_Vt[(size_t)M_*C_];
__device__ __half g_Oh[(size_t)M_*C_];

// ---------------------------------------------------------------------------
// Helpers
// ---------------------------------------------------------------------------
__device__ __forceinline__ void mma_f16(float c[4], const uint32_t a[4], const uint32_t b[2]) {
    asm volatile("mma.sync.aligned.m16n8k16.row.col.f32.f16.f16.f32 "
        "{%0,%1,%2,%3}, {%4,%5,%6,%7}, {%8,%9}, {%0,%1,%2,%3};"
        : "+f"(c[0]), "+f"(c[1]), "+f"(c[2]), "+f"(c[3])
        : "r"(a[0]), "r"(a[1]), "r"(a[2]), "r"(a[3]), "r"(b[0]), "r"(b[1]));
}
__device__ __forceinline__ void ldsm_x4(uint32_t r[4], uint32_t addr) {
    asm volatile("ldmatrix.sync.aligned.m8n8.x4.shared.b16 {%0,%1,%2,%3}, [%4];"
        : "=r"(r[0]), "=r"(r[1]), "=r"(r[2]), "=r"(r[3]) : "r"(addr));
}
__device__ __forceinline__ void ldsm_x4_t(uint32_t r[4], uint32_t addr) {
    asm volatile("ldmatrix.sync.aligned.m8n8.x4.trans.shared.b16 {%0,%1,%2,%3}, [%4];"
        : "=r"(r[0]), "=r"(r[1]), "=r"(r[2]), "=r"(r[3]) : "r"(addr));
}
__device__ __forceinline__ uint32_t pack_h2(float lo, float hi) {
    __half2 h = __floats2half2_rn(lo, hi);     // .x = lo (low 16b)
    return *(uint32_t*)&h;
}
__device__ __forceinline__ void cp16(uint32_t dst, const void* src) {
    asm volatile("cp.async.cg.shared.global [%0], [%1], 16;" :: "r"(dst), "l"(src));
}
#define CP_COMMIT() asm volatile("cp.async.commit_group;")
#define CP_WAIT0()  asm volatile("cp.async.wait_group 0;")
#define CP_WAIT1()  asm volatile("cp.async.wait_group 1;")

__device__ __forceinline__ uint32_t smem_u32(const void* p) {
    uint32_t a;
    asm("{ .reg .u64 t; cvta.to.shared.u64 t, %1; cvt.u32.u64 %0, t; }" : "=r"(a) : "l"(p));
    return a;
}

// ---------------------------------------------------------------------------
// Kernel 0: fused fp32 -> fp16 convert of X, W_qkv, W_proj
// ---------------------------------------------------------------------------
__global__ void cvt_kernel(const float* __restrict__ X,
                           const float* __restrict__ Wq,
                           const float* __restrict__ Wp)
{
    const int stride = gridDim.x * blockDim.x;
    const int tid0 = blockIdx.x * blockDim.x + threadIdx.x;
#pragma unroll 1
    for (int i = tid0; i * 4 < M_*C_; i += stride) {
        const float4 v = *(const float4*)(X + (size_t)i * 4);
        *(__half2*)(g_Xh + (size_t)i*4)     = __floats2half2_rn(v.x, v.y);
        *(__half2*)(g_Xh + (size_t)i*4 + 2) = __floats2half2_rn(v.z, v.w);
    }
#pragma unroll 1
    for (int i = tid0; i * 4 < C_*N3; i += stride) {
        const float4 v = *(const float4*)(Wq + (size_t)i * 4);
        *(__half2*)(g_Wqh + (size_t)i*4)     = __floats2half2_rn(v.x, v.y);
        *(__half2*)(g_Wqh + (size_t)i*4 + 2) = __floats2half2_rn(v.z, v.w);
    }
#pragma unroll 1
    for (int i = tid0; i * 4 < C_*C_; i += stride) {
        const float4 v = *(const float4*)(Wp + (size_t)i * 4);
        *(__half2*)(g_Wph + (size_t)i*4)     = __floats2half2_rn(v.x, v.y);
        *(__half2*)(g_Wph + (size_t)i*4 + 2) = __floats2half2_rn(v.z, v.w);
    }
}

// ---------------------------------------------------------------------------
// fp16 GEMM core (R13 shape): C[128x128], 128 thr / 4 warps, warp tile 64x64
// (4 m-atoms x 8 n-atoms, m16n8k16). A: ldsm.x4; B: ldsm.x4.trans.
// 3-stage cp.async, 1 sync/chunk.
// ---------------------------------------------------------------------------
#define NSTG 3
#define ASTRIDE 40                         // fp16 elems (32 + 8 pad)
#define BSTRIDE 136                        // fp16 elems (128 + 8 pad)
#define AT_B (128*ASTRIDE*2)               // 10240 B
#define BT_B (32*BSTRIDE*2)                // 8704 B
#define STG_B (AT_B + BT_B)                // 18944 B
#define GEMM_SMEM (NSTG*STG_B)             // 56832 B

__device__ __forceinline__ void gemm_prefetch(
    uint32_t smb, const __half* __restrict__ A, int lda,
    const __half* __restrict__ B, int ldb, int m0, int n0,
    int ck, int stage, int tid)
{
    const uint32_t base = smb + (uint32_t)(stage*STG_B);
#pragma unroll
    for (int j = 0; j < 4; j++) {          // A: 128 rows x 32 h = 512 x 16B
        const int f = tid + j*128;
        const int ar = f >> 2, as8 = (f & 3) * 8;
        cp16(base + (uint32_t)(ar*ASTRIDE + as8)*2u,
             A + (size_t)(m0 + ar) * lda + ck*32 + as8);
    }
#pragma unroll
    for (int j = 0; j < 4; j++) {          // B: 32 rows x 128 h = 512 x 16B
        const int f = tid + j*128;
        const int br = f >> 4, bs8 = (f & 15) * 8;
        cp16(base + (uint32_t)AT_B + (uint32_t)(br*BSTRIDE + bs8)*2u,
             B + (size_t)(ck*32 + br) * ldb + n0 + bs8);
    }
    CP_COMMIT();
}

__device__ __forceinline__ void gemm_core(
    const __half* __restrict__ A, int lda,
    const __half* __restrict__ B, int ldb,
    int K, int m0, int n0, uint32_t smb, float acc[4][8][4])
{
    const int tid  = threadIdx.x;
    const int lane = tid & 31;
    const int warp = tid >> 5;
    const int wm = (warp >> 1) * 64;
    const int wn = (warp & 1) * 64;

    const uint32_t a_lane = (uint32_t)((lane & 15)*ASTRIDE + ((lane >> 4) & 1)*8) * 2u;
    const uint32_t b_lane = (uint32_t)(((lane & 7) + ((lane >> 3) & 1)*8)*BSTRIDE
                                       + ((lane >> 4) & 1)*8) * 2u;

    gemm_prefetch(smb, A, lda, B, ldb, m0, n0, 0, 0, tid);
    gemm_prefetch(smb, A, lda, B, ldb, m0, n0, 1, 1, tid);

    const int NCK = K / 32;
    for (int ck = 0; ck < NCK; ck++) {
        if (ck + 2 < NCK) { CP_WAIT1(); } else { CP_WAIT0(); }
        __syncthreads();
        if (ck + 2 < NCK)
            gemm_prefetch(smb, A, lda, B, ldb, m0, n0, ck + 2, (ck + 2) % NSTG, tid);

        const int stg = ck % NSTG;
        const uint32_t aBase = smb + (uint32_t)(stg*STG_B) + a_lane;
        const uint32_t bBase = smb + (uint32_t)(stg*STG_B + AT_B) + b_lane;
#pragma unroll
        for (int ks = 0; ks < 2; ks++) {
            const int k0 = ks*16;
            uint32_t af[4][4];
#pragma unroll
            for (int ma = 0; ma < 4; ma++)
                ldsm_x4(af[ma], aBase + (uint32_t)((wm + ma*16)*ASTRIDE + k0)*2u);
            uint32_t bf[4][4];
#pragma unroll
            for (int j = 0; j < 4; j++)
                ldsm_x4_t(bf[j], bBase + (uint32_t)(k0*BSTRIDE + wn + j*16)*2u);
#pragma unroll
            for (int j = 0; j < 4; j++) {
                uint32_t b0[2] = { bf[j][0], bf[j][1] };
                uint32_t b1[2] = { bf[j][2], bf[j][3] };
#pragma unroll
                for (int ma = 0; ma < 4; ma++) {
                    mma_f16(acc[ma][2*j  ], af[ma], b0);
                    mma_f16(acc[ma][2*j+1], af[ma], b1);
                }
            }
        }
    }
}

// ---------------------------------------------------------------------------
// Kernel 1: QKV GEMM (fp16). Epilogue (fp32 + bias):
//   Q -> fp16((acc+b)/8); K -> fp16(acc+b); V -> fp16 transposed [b,h,d,t]
// ---------------------------------------------------------------------------
__global__ void __launch_bounds__(128, 2) qkv_kernel(const float* __restrict__ bias)
{
    extern __shared__ char smc[];
    const uint32_t smb = smem_u32(smc);
    float acc[4][8][4];
#pragma unroll
    for (int a = 0; a < 4; a++)
#pragma unroll
        for (int b = 0; b < 8; b++)
#pragma unroll
            for (int c = 0; c < 4; c++) acc[a][b][c] = 0.f;

    const int m0 = blockIdx.y * 128;
    const int n0 = blockIdx.x * 128;
    gemm_core(g_Xh, C_, g_Wqh, N3, C_, m0, n0, smb, acc);

    const int lane = threadIdx.x & 31;
    const int warp = threadIdx.x >> 5;
    const int g = lane >> 2, t = lane & 3;
    const int wm = (warp >> 1) * 64;
    const int wn = (warp & 1) * 64;

#pragma unroll
    for (int ma = 0; ma < 4; ma++) {
#pragma unroll
        for (int nb = 0; nb < 8; nb++) {
            const int col = n0 + wn + nb*8 + 2*t;
            const int part = col >> 10;
            const int cc = col & 1023;
            const int h = cc >> 6, d = cc & 63;
            const float b0 = bias[col], b1 = bias[col + 1];
#pragma unroll
            for (int half = 0; half < 2; half++) {
                const int row = m0 + wm + ma*16 + g + half*8;
                const int bb = row >> 11, tt = row & 2047;
                const float x0 = acc[ma][nb][half*2 + 0] + b0;
                const float x1 = acc[ma][nb][half*2 + 1] + b1;
                if (part == 2) {
                    const size_t vb = (size_t)(bb*H_ + h) * D_;
                    g_Vt[(vb + d    ) * T_ + tt] = __float2half_rn(x0);
                    g_Vt[(vb + d + 1) * T_ + tt] = __float2half_rn(x1);
                } else {
                    __half* dst = (part == 0) ? g_Q : g_K;
                    const float scl = (part == 0) ? 0.125f : 1.0f;
                    const size_t idx = ((((size_t)bb*H_ + h)*T_) + tt)*D_ + d;
                    *(__half2*)&dst[idx] = __floats2half2_rn(x0 * scl, x1 * scl);
                }
            }
        }
    }
}

// ---------------------------------------------------------------------------
// Kernel 3: proj GEMM (fp16 in, fp32 out)
// ---------------------------------------------------------------------------
__global__ void __launch_bounds__(128, 2) proj_kernel(
    const float* __restrict__ bias, float* __restrict__ out)
{
    extern __shared__ char smc[];
    const uint32_t smb = smem_u32(smc);
    float acc[4][8][4];
#pragma unroll
    for (int a = 0; a < 4; a++)
#pragma unroll
        for (int b = 0; b < 8; b++)
#pragma unroll
            for (int c = 0; c < 4; c++) acc[a][b][c] = 0.f;

    const int m0 = blockIdx.y * 128;
    const int n0 = blockIdx.x * 128;
    gemm_core(g_Oh, C_, g_Wph, C_, C_, m0, n0, smb, acc);

    const int lane = threadIdx.x & 31;
    const int warp = threadIdx.x >> 5;
    const int g = lane >> 2, t = lane & 3;
    const int wm = (warp >> 1) * 64;
    const int wn = (warp & 1) * 64;

#pragma unroll
    for (int ma = 0; ma < 4; ma++) {
#pragma unroll
        for (int nb = 0; nb < 8; nb++) {
            const int col = n0 + wn + nb*8 + 2*t;
            const float b0 = bias[col], b1 = bias[col + 1];
#pragma unroll
            for (int half = 0; half < 2; half++) {
                const int row = m0 + wm + ma*16 + g + half*8;
                float2 v;
                v.x = acc[ma][nb][half*2 + 0] + b0;
                v.y = acc[ma][nb][half*2 + 1] + b1;
                *(float2*)&out[(size_t)row*C_ + col] = v;
            }
        }
    }
}

// ---------------------------------------------------------------------------
// Kernel 2: flash attention (R13 structure; occupancy raised to 3).
// ---------------------------------------------------------------------------
#define QSTRIDE 72                         // fp16 elems (64 + 8 pad)
#define QS_B  0
#define Q_B_SZ (128*QSTRIDE*2)             // 18432
#define KS_B  Q_B_SZ                       // 18432
#define K_STG_B (64*QSTRIDE*2)             // 9216
#define VT_B  (KS_B + 2*K_STG_B)           // 36864
#define VT_STG_B (64*QSTRIDE*2)            // 9216
#define ATTN_SMEM (VT_B + 2*VT_STG_B)      // 55296

__global__ void __launch_bounds__(128, 3) attn_kernel()
{
    extern __shared__ char smc[];

    const int tid  = threadIdx.x;
    const int lane = tid & 31;
    const int warp = tid >> 5;                 // 0..3
    const int g = lane >> 2, t = lane & 3;
    const int q0 = blockIdx.x * 128;
    const int bh = blockIdx.y;
    const int qr = warp * 32;
    const uint32_t smb = smem_u32(smc);

    const __half* Qg = g_Q + ((size_t)bh*T_ + q0)*D_;
    const __half* Kg = g_K + (size_t)bh*T_*D_;
    const __half* Vtg = g_Vt + (size_t)bh*D_*T_;

    const uint32_t q_lane = (uint32_t)((lane & 15)*QSTRIDE + ((lane >> 4) & 1)*8) * 2u;
    const uint32_t k_lane = (uint32_t)(((lane & 7) + ((lane >> 4) & 1)*8)*QSTRIDE
                                       + ((lane >> 3) & 1)*8) * 2u;
    const uint32_t v_lane = k_lane;

    // Prefetch Q + K/Vt tile 0
#pragma unroll
    for (int it = 0; it < 8; it++) {
        const int f = tid + it*128;
        const int row = f >> 3, c8 = (f & 7) * 8;
        cp16(smb + (uint32_t)(QS_B + (row*QSTRIDE + c8)*2), Qg + (size_t)row*D_ + c8);
    }
#pragma unroll
    for (int it = 0; it < 4; it++) {
        const int f = tid + it*128;
        const int row = f >> 3, c8 = (f & 7) * 8;
        cp16(smb + (uint32_t)(KS_B + (row*QSTRIDE + c8)*2), Kg + (size_t)row*D_ + c8);
        cp16(smb + (uint32_t)(VT_B + (row*QSTRIDE + c8)*2), Vtg + (size_t)row*T_ + c8);
    }
    CP_COMMIT();

    float accO[2][8][4];
#pragma unroll
    for (int ma = 0; ma < 2; ma++)
#pragma unroll
        for (int nb = 0; nb < 8; nb++)
#pragma unroll
            for (int c = 0; c < 4; c++) accO[ma][nb][c] = 0.f;
    float lp[2][2] = {{0.f, 0.f}, {0.f, 0.f}};

    const int NT = T_/64;
    for (int kt = 0; kt < NT; kt++) {
        const int st = kt & 1;
        if (kt + 1 < NT) {
            __syncthreads();
            const int s2 = st ^ 1;
#pragma unroll
            for (int it = 0; it < 4; it++) {
                const int f = tid + it*128;
                const int row = f >> 3, c8 = (f & 7) * 8;
                cp16(smb + (uint32_t)(KS_B + s2*K_STG_B + (row*QSTRIDE + c8)*2),
                     Kg + (size_t)((kt+1)*64 + row)*D_ + c8);
                cp16(smb + (uint32_t)(VT_B + s2*VT_STG_B + (row*QSTRIDE + c8)*2),
                     Vtg + (size_t)row*T_ + (kt+1)*64 + c8);
            }
            CP_COMMIT();
            CP_WAIT1();
        } else {
            CP_WAIT0();
        }
        __syncthreads();

        const uint32_t qBase = smb + q_lane;
        const uint32_t kBase = smb + (uint32_t)(KS_B + st*K_STG_B) + k_lane;
        const uint32_t vBase = smb + (uint32_t)(VT_B + st*VT_STG_B) + v_lane;

        float sacc[2][8][4];
#pragma unroll
        for (int ma = 0; ma < 2; ma++)
#pragma unroll
            for (int nb = 0; nb < 8; nb++)
#pragma unroll
                for (int c = 0; c < 4; c++) sacc[ma][nb][c] = 0.f;

#pragma unroll
        for (int ks = 0; ks < 4; ks++) {
            const int k0 = ks*16;
            uint32_t af[2][4];
#pragma unroll
            for (int ma = 0; ma < 2; ma++)
                ldsm_x4(af[ma], qBase + (uint32_t)((qr + ma*16)*QSTRIDE + k0)*2u);
            uint32_t kf[4][4];
#pragma unroll
            for (int j = 0; j < 4; j++)
                ldsm_x4(kf[j], kBase + (uint32_t)(j*16*QSTRIDE + k0)*2u);
#pragma unroll
            for (int j = 0; j < 4; j++) {
                uint32_t b0[2] = { kf[j][0], kf[j][1] };
                uint32_t b1[2] = { kf[j][2], kf[j][3] };
                mma_f16(sacc[0][2*j  ], af[0], b0);
                mma_f16(sacc[1][2*j  ], af[1], b0);
                mma_f16(sacc[0][2*j+1], af[0], b1);
                mma_f16(sacc[1][2*j+1], af[1], b1);
            }
        }

        uint32_t pf[2][4][4];
#pragma unroll
        for (int ma = 0; ma < 2; ma++) {
#pragma unroll
            for (int nb = 0; nb < 8; nb++) {
                float p0 = __expf(sacc[ma][nb][0]);
                float p1 = __expf(sacc[ma][nb][1]);
                float p2 = __expf(sacc[ma][nb][2]);
                float p3 = __expf(sacc[ma][nb][3]);
                lp[ma][0] += p0 + p1;
                lp[ma][1] += p2 + p3;
                const int ks = nb >> 1, hi = nb & 1;
                pf[ma][ks][hi*2 + 0] = pack_h2(p0, p1);
                pf[ma][ks][hi*2 + 1] = pack_h2(p2, p3);
            }
        }

#pragma unroll
        for (int ks = 0; ks < 4; ks++) {
            const uint32_t kOff = (uint32_t)(ks*16) * 2u;
            uint32_t vf[4][4];
#pragma unroll
            for (int j = 0; j < 4; j++)
                ldsm_x4(vf[j], vBase + (uint32_t)(j*16*QSTRIDE)*2u + kOff);
#pragma unroll
            for (int j = 0; j < 4; j++) {
                uint32_t b0[2] = { vf[j][0], vf[j][1] };
                uint32_t b1[2] = { vf[j][2], vf[j][3] };
                mma_f16(accO[0][2*j  ], pf[0][ks], b0);
                mma_f16(accO[1][2*j  ], pf[1][ks], b0);
                mma_f16(accO[0][2*j+1], pf[0][ks], b1);
                mma_f16(accO[1][2*j+1], pf[1][ks], b1);
            }
        }
    }

    const int b = bh >> 4, h = bh & 15;
#pragma unroll
    for (int ma = 0; ma < 2; ma++) {
        float l0 = lp[ma][0], l1 = lp[ma][1];
        l0 += __shfl_xor_sync(0xffffffffu, l0, 1);
        l0 += __shfl_xor_sync(0xffffffffu, l0, 2);
        l1 += __shfl_xor_sync(0xffffffffu, l1, 1);
        l1 += __shfl_xor_sync(0xffffffffu, l1, 2);
        const float inv0 = 1.f / l0;
        const float inv1 = 1.f / l1;
        const int r0 = q0 + qr + ma*16 + g;
#pragma unroll
        for (int nb = 0; nb < 8; nb++) {
            const int col = h*D_ + nb*8 + 2*t;
            *(__half2*)&g_Oh[((size_t)b*T_ + r0    )*C_ + col] =
                __floats2half2_rn(accO[ma][nb][0]*inv0, accO[ma][nb][1]*inv0);
            *(__half2*)&g_Oh[((size_t)b*T_ + r0 + 8)*C_ + col] =
                __floats2half2_rn(accO[ma][nb][2]*inv1, accO[ma][nb][3]*inv1);
        }
    }
}

// ---------------------------------------------------------------------------
// Launch
// ---------------------------------------------------------------------------
extern "C" void kernel_launch(void* const* d_in, const int* in_sizes, int n_in,
                              void* d_out, int out_size)
{
    (void)in_sizes; (void)n_in; (void)out_size;
    const float* X      = (const float*)d_in[0];
    const float* W_qkv  = (const float*)d_in[1];
    const float* b_qkv  = (const float*)d_in[2];
    const float* W_proj = (const float*)d_in[3];
    const float* b_proj = (const float*)d_in[4];
    float* out = (float*)d_out;

    cudaFuncSetAttribute(qkv_kernel,  cudaFuncAttributeMaxDynamicSharedMemorySize, GEMM_SMEM);
    cudaFuncSetAttribute(proj_kernel, cudaFuncAttributeMaxDynamicSharedMemorySize, GEMM_SMEM);
    cudaFuncSetAttribute(attn_kernel, cudaFuncAttributeMaxDynamicSharedMemorySize, ATTN_SMEM);

    cvt_kernel<<<1184, 256>>>(X, W_qkv, W_proj);

    dim3 g1(N3/128, M_/128);            // (24, 64)
    qkv_kernel<<<g1, 128, GEMM_SMEM>>>(b_qkv);

    dim3 g2(T_/128, B_*H_);             // (16, 64)
    attn_kernel<<<g2, 128, ATTN_SMEM>>>();

    dim3 g3(C_/128, M_/128);            // (8, 64)
    proj_kernel<<<g3, 128, GEMM_SMEM>>>(b_proj, out);
}